// round 5
// baseline (speedup 1.0000x reference)
#include <cuda_runtime.h>

#define BB    4
#define NN    8192
#define NPTS  (BB * NN)
#define ALPHA 5.0f
#define EPS   1e-12f

#define G     36                 // grid cells per dim
#define C     (G * G * G)        // 46656 cells per batch
#define ORIG  (-4.5f)
#define H     0.25f
#define INVH  4.0f

#define SCAN_T 1024
#define CH     ((C + SCAN_T - 1) / SCAN_T)   // 46 cells per scan thread

__device__ int    g_cnt   [BB * C];
__device__ int    g_start [BB * C + 1];
__device__ int    g_cursor[BB * C];
__device__ float4 g_pts   [NPTS];       // (x,y,z, idx-as-float) sorted by cell
__device__ float  g_dsum  [NPTS];
__device__ float  g_bsum  [BB];

__device__ __forceinline__ int cell_of(float v) {
    int c = (int)floorf((v - ORIG) * INVH);
    return min(max(c, 0), G - 1);
}

// ---------------- zero counters / accumulators ----------------
__global__ void k_zero(float* __restrict__ out) {
    int i = blockIdx.x * blockDim.x + threadIdx.x;
    if (i < BB * C) g_cnt[i] = 0;
    if (i == 0) {
        out[0] = 0.0f;
        #pragma unroll
        for (int b = 0; b < BB; b++) g_bsum[b] = 0.0f;
    }
}

// ---------------- count points per cell ----------------
__global__ void k_bin(const float* __restrict__ xyz) {
    int i = blockIdx.x * blockDim.x + threadIdx.x;   // global point index
    if (i >= NPTS) return;
    float x = xyz[3*i], y = xyz[3*i+1], z = xyz[3*i+2];
    int b = i / NN;
    int c = (cell_of(z) * G + cell_of(y)) * G + cell_of(x);
    atomicAdd(&g_cnt[b * C + c], 1);
}

// ---------------- per-batch exclusive prefix sum ----------------
__global__ void __launch_bounds__(SCAN_T) k_scan() {
    __shared__ int sh[SCAN_T];
    int b = blockIdx.x, t = threadIdx.x;
    int base = b * C;
    int c0 = t * CH;

    int s = 0;
    #pragma unroll
    for (int k = 0; k < CH; k++) {
        int c = c0 + k;
        if (c < C) s += g_cnt[base + c];
    }
    sh[t] = s;
    __syncthreads();
    // inclusive Hillis-Steele
    for (int off = 1; off < SCAN_T; off <<= 1) {
        int v = (t >= off) ? sh[t - off] : 0;
        __syncthreads();
        sh[t] += v;
        __syncthreads();
    }
    int run = b * NN + (sh[t] - s);   // batch base + exclusive prefix
    #pragma unroll
    for (int k = 0; k < CH; k++) {
        int c = c0 + k;
        if (c < C) {
            g_start [base + c] = run;
            g_cursor[base + c] = run;
            run += g_cnt[base + c];
        }
    }
    if (b == 0 && t == 0) g_start[BB * C] = NPTS;
}

// ---------------- scatter points into cell-sorted array ----------------
__global__ void k_scatter(const float* __restrict__ xyz) {
    int i = blockIdx.x * blockDim.x + threadIdx.x;
    if (i >= NPTS) return;
    float x = xyz[3*i], y = xyz[3*i+1], z = xyz[3*i+2];
    int b = i / NN;
    int c = (cell_of(z) * G + cell_of(y)) * G + cell_of(x);
    int pos = atomicAdd(&g_cursor[b * C + c], 1);
    g_pts[pos] = make_float4(x, y, z, __int_as_float(i));
}

// ---------------- candidate scan over a contiguous cell row ----------------
__device__ __forceinline__ void scan_row(int rowbase, int x0, int x1, int self,
                                         float px, float py, float pz, float& best) {
    int lo = g_start[rowbase + x0];
    for (int x = x0; x <= x1; x++) {
        int hi = g_start[rowbase + x + 1];
        for (int j = lo; j < hi; j++) {
            float4 r = g_pts[j];
            float ddx = px - r.x, ddy = py - r.y, ddz = pz - r.z;
            float d2 = fmaf(ddx, ddx, fmaf(ddy, ddy, ddz * ddz));
            if (__float_as_int(r.w) != self) best = fminf(best, d2);
        }
        lo = hi;
    }
}

__device__ __forceinline__ float block_reduce_sum(float v) {
    __shared__ float sh[32];
    int lane = threadIdx.x & 31;
    int wid  = threadIdx.x >> 5;
    #pragma unroll
    for (int o = 16; o; o >>= 1) v += __shfl_down_sync(0xFFFFFFFFu, v, o);
    if (lane == 0) sh[wid] = v;
    __syncthreads();
    int nw = (blockDim.x + 31) >> 5;
    v = (threadIdx.x < nw) ? sh[threadIdx.x] : 0.0f;
    if (wid == 0) {
        #pragma unroll
        for (int o = 16; o; o >>= 1) v += __shfl_down_sync(0xFFFFFFFFu, v, o);
    }
    return v;
}

// ---------------- exact NN query + dsum + per-batch sum ----------------
__global__ void k_query(const float* __restrict__ xyz) {
    const int b = blockIdx.y;
    const int n = blockIdx.x * blockDim.x + threadIdx.x;
    const int i = b * NN + n;                 // global point index

    float px = xyz[3*i], py = xyz[3*i+1], pz = xyz[3*i+2];
    int cx = cell_of(px), cy = cell_of(py), cz = cell_of(pz);

    const int bbase = b * C;
    float best = 3.4e38f;

    // R = 1: full 3x3x3 neighborhood (row-contiguous scans)
    {
        int zlo = max(cz-1, 0), zhi = min(cz+1, G-1);
        int ylo = max(cy-1, 0), yhi = min(cy+1, G-1);
        int xlo = max(cx-1, 0), xhi = min(cx+1, G-1);
        for (int z = zlo; z <= zhi; z++)
            for (int y = ylo; y <= yhi; y++)
                scan_row(bbase + (z * G + y) * G, xlo, xhi, i, px, py, pz, best);
    }

    // expand shells until the face-distance guard certifies exactness
    int R = 1;
    while (true) {
        float gxl = (cx - R >= 1)     ? px - (ORIG + (float)(cx - R) * H)     : 3.4e38f;
        float gxh = (cx + R <= G - 2) ? (ORIG + (float)(cx + R + 1) * H) - px : 3.4e38f;
        float gyl = (cy - R >= 1)     ? py - (ORIG + (float)(cy - R) * H)     : 3.4e38f;
        float gyh = (cy + R <= G - 2) ? (ORIG + (float)(cy + R + 1) * H) - py : 3.4e38f;
        float gzl = (cz - R >= 1)     ? pz - (ORIG + (float)(cz - R) * H)     : 3.4e38f;
        float gzh = (cz + R <= G - 2) ? (ORIG + (float)(cz + R + 1) * H) - pz : 3.4e38f;
        float g = fminf(fminf(fminf(gxl, gxh), fminf(gyl, gyh)), fminf(gzl, gzh));
        if (best <= g * g || R >= G) break;

        R++;
        int zlo = max(cz-R, 0), zhi = min(cz+R, G-1);
        int ylo = max(cy-R, 0), yhi = min(cy+R, G-1);
        int xlo = max(cx-R, 0), xhi = min(cx+R, G-1);
        for (int z = zlo; z <= zhi; z++) {
            for (int y = ylo; y <= yhi; y++) {
                int rowbase = bbase + (z * G + y) * G;
                bool face = (abs(z - cz) == R) || (abs(y - cy) == R);
                if (face) {
                    scan_row(rowbase, xlo, xhi, i, px, py, pz, best);
                } else {
                    if (cx - R >= 0)     scan_row(rowbase, cx - R, cx - R, i, px, py, pz, best);
                    if (cx + R <= G - 1) scan_row(rowbase, cx + R, cx + R, i, px, py, pz, best);
                }
            }
        }
    }

    // self term via the same expanded-form fma chain as the reference path
    float w = (px*px + py*py) + pz*pz;
    float mself = fmaf(-2.0f*px, px, fmaf(-2.0f*py, py, fmaf(-2.0f*pz, pz, w)));
    float d2self = w + mself;

    float ds = sqrtf(fmaxf(d2self, EPS)) + sqrtf(fmaxf(best, EPS));
    g_dsum[i] = ds;

    float t = block_reduce_sum(ds);
    if (threadIdx.x == 0) atomicAdd(&g_bsum[b], t);
}

// ---------------- masked loss: dsum > (bsum/N) * ALPHA ----------------
__global__ void k_loss(float* __restrict__ out) {
    int b = blockIdx.x >> 5;                 // 32 blocks per batch
    int chunk = blockIdx.x & 31;
    float avg = g_bsum[b] / (float)NN;       // mean first, then *ALPHA (ref op order)
    float thr = avg * ALPHA;
    float d = g_dsum[b * NN + chunk * 256 + threadIdx.x];
    float s = (d > thr) ? d : 0.0f;
    s = block_reduce_sum(s);
    if (threadIdx.x == 0) atomicAdd(out, s);
}

extern "C" void kernel_launch(void* const* d_in, const int* in_sizes, int n_in,
                              void* d_out, int out_size) {
    const float* xyz = (const float*)d_in[0];
    float* out = (float*)d_out;

    k_zero<<<(BB * C + 511) / 512, 512>>>(out);
    k_bin<<<NPTS / 256, 256>>>(xyz);
    k_scan<<<BB, SCAN_T>>>();
    k_scatter<<<NPTS / 256, 256>>>(xyz);

    dim3 qgrid(NN / 256, BB);
    k_query<<<qgrid, 256>>>(xyz);

    k_loss<<<BB * 32, 256>>>(out);
}

// round 6
// speedup vs baseline: 6.7284x; 6.7284x over previous
#include <cuda_runtime.h>

#define BB    4
#define NN    8192
#define ALPHA 5.0f
#define EPS   1e-12f

#define SPLIT  8                 // ref-dimension split
#define SLICE  (NN / SPLIT)      // 1024 refs per block
#define SLICEP (SLICE / 2)       // 512 ref pairs (16 KB smem)
#define QB     128               // threads per knn block
#define QPT    2                 // queries per thread
#define QBLK   (QB * QPT)        // 256 queries per block
#define GX     (NN / QBLK)       // 32 query-blocks per batch
#define MBLKS  (NN / 256)        // 32 merge blocks per batch

typedef unsigned long long ull;

__device__ float g_part[BB * SPLIT * NN]; // per-(batch,slice,query) partial min
__device__ float g_dsum[BB * NN];
__device__ float g_bsum[BB];
__device__ int   g_done[BB];

__device__ __forceinline__ ull f2u(float a, float b) {
    union { float f[2]; ull u; } t; t.f[0] = a; t.f[1] = b; return t.u;
}
__device__ __forceinline__ void u2f(ull v, float& a, float& b) {
    union { float f[2]; ull u; } t; t.u = v; a = t.f[0]; b = t.f[1];
}
__device__ __forceinline__ ull fma2(ull a, ull b, ull c) {
    ull d; asm("fma.rn.f32x2 %0, %1, %2, %3;" : "=l"(d) : "l"(a), "l"(b), "l"(c)); return d;
}

// Each block: 256 queries (2/thread) vs a 1024-ref slice; the slice is loaded
// from raw xyz and packed into smem in-kernel (no prep kernel, no global
// packed arrays). Emits per-query partial m = min over slice of (w_j - 2*dot).
// The 1-in-8 block whose slice contains its own queries runs exact 2-min and
// emits the second smallest (self is that slice's strict min).
__global__ void __launch_bounds__(QB) k_knn(const float* __restrict__ xyz,
                                            float* __restrict__ out) {
    __shared__ float4 sA[SLICEP];   // {x0,x1,y0,y1} per ref pair
    __shared__ float4 sB[SLICEP];   // {z0,z1,w0,w1}

    const int b     = blockIdx.y;
    const int slice = blockIdx.z;
    const int tid   = threadIdx.x;

    // one thread zeroes the epilogue accumulators (merge runs after knn)
    if (blockIdx.x == 0 && slice == 0 && tid == 0) {
        if (b == 0) out[0] = 0.0f;
        g_bsum[b] = 0.0f;
        g_done[b] = 0;
    }

    // load + pack this block's slice: thread t handles pairs t, t+128, ...
    const float* __restrict__ src = xyz + (size_t)(b * NN + slice * SLICE) * 3;
    #pragma unroll
    for (int k = 0; k < SLICEP / QB; k++) {          // 4 pairs/thread
        int q = tid + k * QB;
        float x0 = src[6*q+0], y0 = src[6*q+1], z0 = src[6*q+2];
        float x1 = src[6*q+3], y1 = src[6*q+4], z1 = src[6*q+5];
        float w0 = (x0*x0 + y0*y0) + z0*z0;
        float w1 = (x1*x1 + y1*y1) + z1*z1;
        sA[q] = make_float4(x0, x1, y0, y1);
        sB[q] = make_float4(z0, z1, w0, w1);
    }

    // queries straight from xyz
    const int qbase = blockIdx.x * QBLK + tid;
    ull mx[QPT], my[QPT], mz[QPT];
    #pragma unroll
    for (int k = 0; k < QPT; k++) {
        const float* qp = xyz + (size_t)(b * NN + qbase + k * QB) * 3;
        float qx = qp[0], qy = qp[1], qz = qp[2];
        mx[k] = f2u(-2.0f*qx, -2.0f*qx);
        my[k] = f2u(-2.0f*qy, -2.0f*qy);
        mz[k] = f2u(-2.0f*qz, -2.0f*qz);
    }

    __syncthreads();

    const bool self_block = (slice == (blockIdx.x >> 2));  // QBLK*4 == SLICE
    float part[QPT];

    if (!self_block) {
        // fast path: plain min, 4 independent accumulators per query
        float a0[QPT], a1[QPT], a2[QPT], a3[QPT];
        #pragma unroll
        for (int k = 0; k < QPT; k++) { a0[k]=a1[k]=a2[k]=a3[k]=3.4e38f; }

        #pragma unroll 2
        for (int j = 0; j < SLICEP; j += 2) {
            float4 A0 = sA[j],   B0 = sB[j];
            float4 A1 = sA[j+1], B1 = sB[j+1];
            ull x0 = f2u(A0.x, A0.y), y0 = f2u(A0.z, A0.w);
            ull z0 = f2u(B0.x, B0.y), w0 = f2u(B0.z, B0.w);
            ull x1 = f2u(A1.x, A1.y), y1 = f2u(A1.z, A1.w);
            ull z1 = f2u(B1.x, B1.y), w1 = f2u(B1.z, B1.w);
            #pragma unroll
            for (int k = 0; k < QPT; k++) {
                ull t0 = fma2(mx[k], x0, fma2(my[k], y0, fma2(mz[k], z0, w0)));
                ull t1 = fma2(mx[k], x1, fma2(my[k], y1, fma2(mz[k], z1, w1)));
                float c0, c1, c2, c3;
                u2f(t0, c0, c1); u2f(t1, c2, c3);
                a0[k] = fminf(a0[k], c0);
                a1[k] = fminf(a1[k], c1);
                a2[k] = fminf(a2[k], c2);
                a3[k] = fminf(a3[k], c3);
            }
        }
        #pragma unroll
        for (int k = 0; k < QPT; k++)
            part[k] = fminf(fminf(a0[k], a1[k]), fminf(a2[k], a3[k]));
    } else {
        // self path: exact 2-min; emit second smallest (min excluding self)
        float s0[QPT], s1[QPT];
        #pragma unroll
        for (int k = 0; k < QPT; k++) { s0[k] = 3.4e38f; s1[k] = 3.4e38f; }

        for (int j = 0; j < SLICEP; j += 2) {
            float4 A0 = sA[j],   B0 = sB[j];
            float4 A1 = sA[j+1], B1 = sB[j+1];
            ull x0 = f2u(A0.x, A0.y), y0 = f2u(A0.z, A0.w);
            ull z0 = f2u(B0.x, B0.y), w0 = f2u(B0.z, B0.w);
            ull x1 = f2u(A1.x, A1.y), y1 = f2u(A1.z, A1.w);
            ull z1 = f2u(B1.x, B1.y), w1 = f2u(B1.z, B1.w);
            #pragma unroll
            for (int k = 0; k < QPT; k++) {
                ull t0 = fma2(mx[k], x0, fma2(my[k], y0, fma2(mz[k], z0, w0)));
                ull t1 = fma2(mx[k], x1, fma2(my[k], y1, fma2(mz[k], z1, w1)));
                float c0, c1, c2, c3;
                u2f(t0, c0, c1); u2f(t1, c2, c3);
                float m1 = fminf(c0, c1), M1 = fmaxf(c0, c1);
                float m2 = fminf(c2, c3), M2 = fmaxf(c2, c3);
                float v0 = fminf(m1, m2);
                float v1 = fminf(fmaxf(m1, m2), fminf(M1, M2));
                float n0 = fminf(v0, s0[k]);
                float tt = fmaxf(v0, s0[k]);
                float uu = fminf(v1, s1[k]);
                s0[k] = n0; s1[k] = fminf(tt, uu);
            }
        }
        #pragma unroll
        for (int k = 0; k < QPT; k++) part[k] = s1[k];
    }

    float* dst = &g_part[(b * SPLIT + slice) * NN];
    #pragma unroll
    for (int k = 0; k < QPT; k++) dst[qbase + k * QB] = part[k];
}

__device__ __forceinline__ float block_reduce_sum(float v) {
    __shared__ float sh[32];
    int lane = threadIdx.x & 31;
    int wid  = threadIdx.x >> 5;
    #pragma unroll
    for (int o = 16; o; o >>= 1) v += __shfl_down_sync(0xFFFFFFFFu, v, o);
    if (lane == 0) sh[wid] = v;
    __syncthreads();
    int nw = (blockDim.x + 31) >> 5;
    v = (threadIdx.x < nw) ? sh[threadIdx.x] : 0.0f;
    if (wid == 0) {
        #pragma unroll
        for (int o = 16; o; o >>= 1) v += __shfl_down_sync(0xFFFFFFFFu, v, o);
    }
    return v;
}

// One thread per query: merge SPLIT partial mins, add ||q||^2, self-distance,
// dsum + batch-sum; the LAST block of each batch computes the masked loss.
__global__ void k_merge(const float* __restrict__ xyz, float* __restrict__ out) {
    const int i = blockIdx.x * blockDim.x + threadIdx.x;   // global query idx
    const int b = i / NN;
    const int q = i - b * NN;

    float m = g_part[(b * SPLIT + 0) * NN + q];
    #pragma unroll
    for (int s = 1; s < SPLIT; s++)
        m = fminf(m, g_part[(b * SPLIT + s) * NN + q]);

    const float* p = xyz + (size_t)i * 3;
    float px = p[0], py = p[1], pz = p[2];
    float w = (px*px + py*py) + pz*pz;
    float d2nn = w + m;   // ||q||^2 + min_j(w_j - 2 dot_j)
    float mself = fmaf(-2.0f*px, px, fmaf(-2.0f*py, py, fmaf(-2.0f*pz, pz, w)));
    float d2self = w + mself;

    float ds = sqrtf(fmaxf(d2self, EPS)) + sqrtf(fmaxf(d2nn, EPS));
    g_dsum[i] = ds;

    float t = block_reduce_sum(ds);

    __shared__ int lastflag;
    if (threadIdx.x == 0) {
        atomicAdd(&g_bsum[b], t);
        __threadfence();
        int d = atomicAdd(&g_done[b], 1);
        lastflag = (d == MBLKS - 1);
    }
    __syncthreads();

    if (lastflag) {
        // all 32 blocks of this batch have published dsum + bsum (fence+counter)
        float total = atomicAdd(&g_bsum[b], 0.0f);     // coherent read via L2
        float thr = (total / (float)NN) * ALPHA;       // mean, then *ALPHA (ref order)
        float s = 0.0f;
        for (int j = threadIdx.x; j < NN; j += blockDim.x) {
            float d = g_dsum[b * NN + j];
            if (d > thr) s += d;
        }
        s = block_reduce_sum(s);
        if (threadIdx.x == 0) atomicAdd(out, s);
    }
}

extern "C" void kernel_launch(void* const* d_in, const int* in_sizes, int n_in,
                              void* d_out, int out_size) {
    const float* xyz = (const float*)d_in[0];
    float* out = (float*)d_out;

    dim3 grid(GX, BB, SPLIT);            // 32 x 4 x 8 = 1024 blocks
    k_knn<<<grid, QB>>>(xyz, out);

    k_merge<<<BB * MBLKS, 256>>>(xyz, out);
}